// round 16
// baseline (speedup 1.0000x reference)
#include <cuda_runtime.h>
#include <cuda_fp16.h>
#include <cstdint>

// vaeVectorQuantizer: x[N=131072, D=64], E[D=64, K=1024]
// fp16 h1xh1 approx GEMM (mma.sync.m16n8k16) with e_sq and +16 bias FOLDED
// INTO THE MMA (5th fragment slot) => argmin(key) == argmax(acc), acc > 0.
// Epilogue: packed (acc_bits&~0x3FF)|(1023-code), top-2 via 3 min/max + 1 LOP3
// per key. Rows with packed gap < EPS_ACC get exact fp32 coalesced rescan
// (reference rounding, tie->lowest). occupancy 3.

#define D_DIM 64
#define K_DIM 1024
#define ROWS_PER_CTA 64
#define NTILE 128
#define NTILES 8
#define MTHREADS 256
#define EPS_ACC 8e-3f

#define PADROW 144
#define SM_X     0                         // 64 * 144 = 9216
#define SM_B     9216
#define B_BYTES  (NTILE * 64 * 2 + 4096)   // 20480: 4 kc slots + esq/bias slot
#define SM_ESQ   (SM_B + 2 * B_BYTES)      // 50176
#define SM_YS    (SM_ESQ + 4096)           // 54272
#define SM_MRG   (SM_YS + 256)             // 54528: qv[4][64], qv2[4][64] (uint)
#define SM_CIDX  (SM_MRG + 2048)           // 56576
#define SM_XROW  (SM_CIDX + 256)           // 56832
#define SM_LIST  (SM_XROW + 256)           // 57088
#define SM_CNT   (SM_LIST + 256)           // 57344
#define SM_WRED  (SM_CNT + 16)             // 57360
#define SM_TOTAL 57472

__device__ float g_esq[K_DIM];
__device__ float g_ET[K_DIM * D_DIM];          // [k][d] fp32: gather table
__device__ uint2 g_Bf[NTILES * 5 * 16 * 32];   // [t][slot0..4][nf][lane]

__device__ __forceinline__ uint32_t smem_u32(const void* p) {
    uint32_t a;
    asm("{ .reg .u64 t; cvta.to.shared.u64 t, %1; cvt.u32.u64 %0, t; }" : "=r"(a) : "l"(p));
    return a;
}
__device__ __forceinline__ void cp16(uint32_t dst, const void* src) {
    asm volatile("cp.async.cg.shared.global [%0], [%1], 16;" :: "r"(dst), "l"(src));
}
#define CP_COMMIT() asm volatile("cp.async.commit_group;" ::: "memory")
#define CP_WAIT(N)  asm volatile("cp.async.wait_group %0;" :: "n"(N) : "memory")

__device__ __forceinline__ void mma16816h(float* c, uint32_t a0, uint32_t a1,
                                          uint32_t a2, uint32_t a3,
                                          uint32_t b0, uint32_t b1) {
    asm volatile(
        "mma.sync.aligned.m16n8k16.row.col.f32.f16.f16.f32 "
        "{%0,%1,%2,%3}, {%4,%5,%6,%7}, {%8,%9}, {%0,%1,%2,%3};"
        : "+f"(c[0]), "+f"(c[1]), "+f"(c[2]), "+f"(c[3])
        : "r"(a0), "r"(a1), "r"(a2), "r"(a3), "r"(b0), "r"(b1));
}

// compensated accumulate of v*v (exact product + 2Sum) — no FP64 anywhere
__device__ __forceinline__ void csq(float v, float& s, float& comp) {
    float p = v * v;
    float e = fmaf(v, v, -p);
    float hi = s + p;
    float bb = hi - s;
    float err = (s - (hi - bb)) + (p - bb);
    s = hi;
    comp += err + e;
}
__device__ __forceinline__ void cmerge(float os, float ocmp, float& s, float& comp) {
    float hi = s + os;
    float bb = hi - s;
    float err = (s - (hi - bb)) + (os - bb);
    s = hi;
    comp += ocmp + err;
}

// pack positive float key + 10-bit reversed code (ordering preserved as uint)
__device__ __forceinline__ uint32_t packk(float f, int rev) {
    return (__float_as_uint(f) & 0xFFFFFC00u) | (uint32_t)rev;
}
// top-2 max tracking: v2 = max(v2, min(v1,k)); v1 = max(v1,k)
__device__ __forceinline__ void trk(uint32_t kp, uint32_t& v1, uint32_t& v2) {
    uint32_t t = min(v1, kp);
    v2 = max(v2, t);
    v1 = max(v1, kp);
}

// ---------------- prep: coalesced e_sq + transposed gather table ----------------
__global__ void vq_prep(const float* __restrict__ E) {
    __shared__ float T[64][33];
    const int tid = threadIdx.x, lane = tid & 31, w = tid >> 5;
    const int k0 = blockIdx.x * 32;
#pragma unroll
    for (int dd = 0; dd < 8; ++dd) {
        int d = w * 8 + dd;
        T[d][lane] = E[d * K_DIM + k0 + lane];
    }
    __syncthreads();
    const int k = tid >> 3;
    const int dseg = (tid & 7) * 8;
    float s = 0.f, comp = 0.f;
#pragma unroll
    for (int j = 0; j < 8; ++j) csq(T[dseg + j][k], s, comp);
#pragma unroll
    for (int off = 1; off <= 4; off <<= 1) {
        float os   = __shfl_xor_sync(0xffffffffu, s, off);
        float ocmp = __shfl_xor_sync(0xffffffffu, comp, off);
        cmerge(os, ocmp, s, comp);
    }
    if ((tid & 7) == 0) g_esq[k0 + k] = s + comp;
    float4 a, b;
    a.x = T[dseg + 0][k]; a.y = T[dseg + 1][k]; a.z = T[dseg + 2][k]; a.w = T[dseg + 3][k];
    b.x = T[dseg + 4][k]; b.y = T[dseg + 5][k]; b.z = T[dseg + 6][k]; b.w = T[dseg + 7][k];
    *(float4*)(g_ET + (k0 + k) * D_DIM + dseg)     = a;
    *(float4*)(g_ET + (k0 + k) * D_DIM + dseg + 4) = b;
}

// ---------------- prep: B fragments (4 kc slots + esq/bias slot) ----------------
// slot<4: E_h1[d][code], d = kc*16 + (lane%4)*2 + m*8 + j, code = t*128+nf*8+lane/4
// slot==4: k=0 -> 16.0, k=1 -> -0.5*e_sq[code] (lanes with lane%4==0), rest 0.
__global__ void vq_prep_b(const float* __restrict__ E) {
    int idx = blockIdx.x * blockDim.x + threadIdx.x;   // 20480 total
    int lane = idx & 31;
    int nf = (idx >> 5) & 15;
    int x2 = idx >> 9;
    int slot = x2 % 5;
    int t = x2 / 5;

    int code = t * 128 + nf * 8 + (lane >> 2);
    int c = lane & 3;
    uint2 r = make_uint2(0u, 0u);
    if (slot < 4) {
        int kc = slot;
#pragma unroll
        for (int m = 0; m < 2; ++m) {
            int d0 = kc * 16 + c * 2 + m * 8;
            __half2 pk = __halves2half2(__float2half_rn(E[d0 * K_DIM + code]),
                                        __float2half_rn(E[(d0 + 1) * K_DIM + code]));
            ((uint32_t*)&r)[m] = *(uint32_t*)&pk;
        }
    } else if (c == 0) {
        __half2 pk = __halves2half2(__float2half_rn(16.0f),
                                    __float2half_rn(-0.5f * g_esq[code]));
        r.x = *(uint32_t*)&pk;
    }
    g_Bf[idx] = r;
}

// ---------------- main ----------------
__global__ __launch_bounds__(MTHREADS, 3)
void vq_tc(const float* __restrict__ x, const float* __restrict__ E,
           float* __restrict__ out) {
    extern __shared__ __align__(16) char smem[];
    const int tid = threadIdx.x;
    const int wid = tid >> 5;
    const int lane = tid & 31;
    const size_t rowbase = (size_t)blockIdx.x * ROWS_PER_CTA;

    float* esq_s = (float*)(smem + SM_ESQ);
    float* ys_sh = (float*)(smem + SM_YS);
    int*   cidx  = (int*)(smem + SM_CIDX);
    const uint32_t sB_u32 = smem_u32(smem + SM_B);

    *(float4*)(esq_s + 4 * tid) = *(const float4*)(g_esq + 4 * tid);
    if (tid == 0) *(int*)(smem + SM_CNT) = 0;

    // ---- prefetch B tile 0 (20KB)
    {
        const char* src = (const char*)g_Bf;
#pragma unroll
        for (int i = 0; i < 5; ++i)
            cp16(sB_u32 + i * 4096 + tid * 16, src + i * 4096 + tid * 16);
        CP_COMMIT();
    }

    // ---- x: h1 fp16 into padded smem + compensated-fp32 row norms
    {
        int r = tid >> 2, dq = (tid & 3) * 16;
        const float* xr = x + (rowbase + r) * D_DIM + dq;
        char* xs = smem + SM_X + r * PADROW;
        float s = 0.f, comp = 0.f;
#pragma unroll
        for (int i = 0; i < 4; ++i) {
            float4 v = *(const float4*)(xr + 4 * i);
            int d0 = dq + 4 * i;
            csq(v.x, s, comp); csq(v.y, s, comp);
            csq(v.z, s, comp); csq(v.w, s, comp);
            *(__half2*)(xs + d0 * 2)     = __halves2half2(__float2half_rn(v.x), __float2half_rn(v.y));
            *(__half2*)(xs + d0 * 2 + 4) = __halves2half2(__float2half_rn(v.z), __float2half_rn(v.w));
        }
#pragma unroll
        for (int off = 1; off <= 2; off <<= 1) {
            float os   = __shfl_xor_sync(0xffffffffu, s, off);
            float ocmp = __shfl_xor_sync(0xffffffffu, comp, off);
            cmerge(os, ocmp, s, comp);
        }
        if ((tid & 3) == 0) ys_sh[r] = s + comp;
    }

    const int cq = wid >> 1;           // column quarter (32 codes)
    const int wg = wid & 1;            // row group (32 rows)
    const int g = lane >> 2, c = lane & 3;
    const uint32_t aex = (c == 0) ? 0x3C003C00u : 0u;  // half2(1,1) at k=0,1

    __syncthreads();

    const char* aRow[2][2];
#pragma unroll
    for (int mf = 0; mf < 2; ++mf)
#pragma unroll
        for (int h = 0; h < 2; ++h)
            aRow[mf][h] = smem + SM_X + (wg * 32 + mf * 16 + h * 8 + g) * PADROW + c * 4;

    uint32_t v1p[2][2] = {{0u, 0u}, {0u, 0u}};
    uint32_t v2p[2][2] = {{0u, 0u}, {0u, 0u}};

    for (int t = 0; t < NTILES; ++t) {
        const int buf = t & 1;
        if (t + 1 < NTILES) {
            const char* src = (const char*)g_Bf + (t + 1) * B_BYTES;
            uint32_t dst = sB_u32 + (buf ^ 1) * B_BYTES;
#pragma unroll
            for (int i = 0; i < 5; ++i)
                cp16(dst + i * 4096 + tid * 16, src + i * 4096 + tid * 16);
            CP_COMMIT();
            CP_WAIT(1);
        } else {
            CP_WAIT(0);
        }
        __syncthreads();

        float acc[4][2][4];
#pragma unroll
        for (int nf = 0; nf < 4; ++nf)
#pragma unroll
            for (int mf = 0; mf < 2; ++mf)
#pragma unroll
                for (int j = 0; j < 4; ++j) acc[nf][mf][j] = 0.f;

#pragma unroll
        for (int kc = 0; kc < 4; ++kc) {
            uint32_t A[2][4];
#pragma unroll
            for (int mf = 0; mf < 2; ++mf) {
                const char* a0p = aRow[mf][0] + kc * 32;
                const char* a1p = aRow[mf][1] + kc * 32;
                A[mf][0] = *(const uint32_t*)(a0p);
                A[mf][1] = *(const uint32_t*)(a1p);
                A[mf][2] = *(const uint32_t*)(a0p + 16);
                A[mf][3] = *(const uint32_t*)(a1p + 16);
            }
            const uint2* bp = (const uint2*)(smem + SM_B + buf * B_BYTES + kc * 4096)
                              + cq * 128 + lane;
            uint2 B[4];
#pragma unroll
            for (int nf = 0; nf < 4; ++nf) B[nf] = bp[nf * 32];
#pragma unroll
            for (int mf = 0; mf < 2; ++mf)
#pragma unroll
                for (int nf = 0; nf < 4; ++nf)
                    mma16816h(acc[nf][mf], A[mf][0], A[mf][1], A[mf][2], A[mf][3],
                              B[nf].x, B[nf].y);
        }
        // ---- esq/bias slot: acc += 1*16 + 1*(-esq/2)
        {
            const uint2* bp = (const uint2*)(smem + SM_B + buf * B_BYTES + 4 * 4096)
                              + cq * 128 + lane;
            uint2 B[4];
#pragma unroll
            for (int nf = 0; nf < 4; ++nf) B[nf] = bp[nf * 32];
#pragma unroll
            for (int mf = 0; mf < 2; ++mf)
#pragma unroll
                for (int nf = 0; nf < 4; ++nf)
                    mma16816h(acc[nf][mf], aex, aex, 0u, 0u, B[nf].x, B[nf].y);
        }

        // ---- packed top-2 tracking: 1 LOP3 + 3 min/max per key
        const int Rb = 1023 - (t * NTILE + cq * 32 + 2 * c);
#pragma unroll
        for (int nf = 0; nf < 4; ++nf) {
            const int r0 = Rb - nf * 8, r1 = r0 - 1;
#pragma unroll
            for (int mf = 0; mf < 2; ++mf) {
                trk(packk(acc[nf][mf][0], r0), v1p[mf][0], v2p[mf][0]);
                trk(packk(acc[nf][mf][1], r1), v1p[mf][0], v2p[mf][0]);
                trk(packk(acc[nf][mf][2], r0), v1p[mf][1], v2p[mf][1]);
                trk(packk(acc[nf][mf][3], r1), v1p[mf][1], v2p[mf][1]);
            }
        }
        __syncthreads();
    }

    // ---- merge across the 4 lanes (c) sharing each row
#pragma unroll
    for (int off = 1; off <= 2; off <<= 1) {
#pragma unroll
        for (int mf = 0; mf < 2; ++mf)
#pragma unroll
            for (int h = 0; h < 2; ++h) {
                uint32_t o1 = __shfl_xor_sync(0xffffffffu, v1p[mf][h], off);
                uint32_t o2 = __shfl_xor_sync(0xffffffffu, v2p[mf][h], off);
                uint32_t tt = min(v1p[mf][h], o1);
                v2p[mf][h] = max(max(v2p[mf][h], o2), tt);
                v1p[mf][h] = max(v1p[mf][h], o1);
            }
    }
    // ---- publish per-quarter packed top-2, merge across quarters
    uint32_t* qv  = (uint32_t*)(smem + SM_MRG);      // [cq][row]
    uint32_t* qv2 = (uint32_t*)(smem + SM_MRG + 1024);
    if (c == 0) {
#pragma unroll
        for (int mf = 0; mf < 2; ++mf)
#pragma unroll
            for (int h = 0; h < 2; ++h) {
                int r = cq * 64 + wg * 32 + mf * 16 + h * 8 + g;
                qv[r] = v1p[mf][h]; qv2[r] = v2p[mf][h];
            }
    }
    __syncthreads();
    int* list = (int*)(smem + SM_LIST);
    int* cnt  = (int*)(smem + SM_CNT);
    if (tid < ROWS_PER_CTA) {
        uint32_t V1 = qv[tid], V2 = qv2[tid];
#pragma unroll
        for (int q = 1; q < 4; ++q) {
            uint32_t o1 = qv[q * 64 + tid], o2 = qv2[q * 64 + tid];
            uint32_t tt = min(V1, o1);
            V2 = max(max(V2, o2), tt);
            V1 = max(V1, o1);
        }
        cidx[tid] = 1023 - (int)(V1 & 1023u);
        float g1 = __uint_as_float(V1 & 0xFFFFFC00u);
        float g2 = __uint_as_float(V2 & 0xFFFFFC00u);
        if (g1 - g2 < EPS_ACC) {       // ambiguous under approx error -> exact rescan
            int slot = atomicAdd(cnt, 1);
            list[slot] = tid;
        }
    }
    __syncthreads();

    // ---- exact fp32 rescan of flagged rows (reference rounding, tie->lowest)
    const int nflag = *cnt;
    float* xrow = (float*)(smem + SM_XROW);
    float* wrv  = (float*)(smem + SM_WRED);
    int*   wrc  = (int*)(smem + SM_WRED + 32);
    for (int i = 0; i < nflag; ++i) {
        int r = list[i];
        if (tid < 16)
            ((float4*)xrow)[tid] = ((const float4*)(x + (rowbase + r) * D_DIM))[tid];
        __syncthreads();
        float ys = ys_sh[r];
        float dot[4] = {0.f, 0.f, 0.f, 0.f};
#pragma unroll
        for (int d = 0; d < D_DIM; ++d) {
            float xv = xrow[d];
            const float* Ed = E + d * K_DIM + tid;
#pragma unroll
            for (int kk = 0; kk < 4; ++kk)
                dot[kk] = fmaf(xv, Ed[kk * MTHREADS], dot[kk]);
        }
        float bestv = 3.402823466e38f;
        int   bestc = 0;
#pragma unroll
        for (int kk = 0; kk < 4; ++kk) {
            int k = tid + kk * MTHREADS;
            float key = fmaf(-2.f, dot[kk], __fadd_rn(ys, esq_s[k]));
            if (key < bestv || (key == bestv && k < bestc)) { bestv = key; bestc = k; }
        }
#pragma unroll
        for (int off = 16; off >= 1; off >>= 1) {
            float ov = __shfl_xor_sync(0xffffffffu, bestv, off);
            int   oc = __shfl_xor_sync(0xffffffffu, bestc, off);
            if (ov < bestv || (ov == bestv && oc < bestc)) { bestv = ov; bestc = oc; }
        }
        if (lane == 0) { wrv[wid] = bestv; wrc[wid] = bestc; }
        __syncthreads();
        if (tid == 0) {
            float bv = wrv[0]; int bcn = wrc[0];
#pragma unroll
            for (int w = 1; w < 8; ++w) {
                float v = wrv[w]; int cc = wrc[w];
                if (v < bv || (v == bv && cc < bcn)) { bv = v; bcn = cc; }
            }
            cidx[r] = bcn;
        }
        __syncthreads();
    }

    // ---- gather output rows from transposed codebook
    float* og = out + rowbase * D_DIM;
#pragma unroll
    for (int it = 0; it < 4; ++it) {
        int i  = tid + it * MTHREADS;
        int r  = i >> 4;
        int d0 = (i & 15) << 2;
        *(float4*)(og + r * D_DIM + d0) = *(const float4*)(g_ET + cidx[r] * D_DIM + d0);
    }
}

extern "C" void kernel_launch(void* const* d_in, const int* in_sizes, int n_in,
                              void* d_out, int out_size) {
    const float* x = (const float*)d_in[0];
    const float* E = (const float*)d_in[1];
    float* out = (float*)d_out;
    int N = in_sizes[0] / D_DIM;  // 131072

    cudaFuncSetAttribute(vq_tc, cudaFuncAttributeMaxDynamicSharedMemorySize, SM_TOTAL);
    vq_prep<<<K_DIM / 32, MTHREADS>>>(E);
    vq_prep_b<<<(NTILES * 5 * 16 * 32) / MTHREADS, MTHREADS>>>(E);
    vq_tc<<<N / ROWS_PER_CTA, MTHREADS, SM_TOTAL>>>(x, E, out);
}